// round 1
// baseline (speedup 1.0000x reference)
#include <cuda_runtime.h>
#include <cuda_bf16.h>

// Reference collapses: softmax over a size-1 axis == 1.0, so the attention
// weight is identically 1 and out == depthwise 3x3 conv(x, wv, pad=1).
// (XLA conv_general_dilated is cross-correlation: no kernel flip.)
//
// Shapes: x (8, 256, 128, 128) f32, wv (256, 1, 3, 3) f32 -> out same as x.
// Pure HBM-streaming kernel: 128 MiB in + 128 MiB out per pass.

#define Bn 8
#define Cn 256
#define Hn 128
#define Wn 128
#define ROWS 8   // rows per block

__global__ __launch_bounds__(256) void dwconv3x3_kernel(
    const float* __restrict__ x,
    const float* __restrict__ wv,
    float* __restrict__ out)
{
    const int tx = threadIdx.x;            // 0..31  -> column quad
    const int ty = threadIdx.y;            // 0..7   -> row within block
    const int c  = blockIdx.y;             // channel
    const int b  = blockIdx.z;             // batch
    const int y  = blockIdx.x * ROWS + ty; // output row
    const int xq = tx * 4;                 // leftmost output column of quad

    // Per-channel 3x3 weights
    const float* wp = wv + c * 9;
    float w[9];
#pragma unroll
    for (int k = 0; k < 9; ++k) w[k] = __ldg(wp + k);

    const float* img = x + ((size_t)(b * Cn + c)) * (Hn * Wn);

    float acc0 = 0.f, acc1 = 0.f, acc2 = 0.f, acc3 = 0.f;

#pragma unroll
    for (int dy = 0; dy < 3; ++dy) {
        const int yy = y + dy - 1;
        if (yy < 0 || yy >= Hn) continue;   // zero padding top/bottom
        const float* row = img + yy * Wn;

        const float4 cen = *reinterpret_cast<const float4*>(row + xq);
        const float l = (tx > 0)  ? __ldg(row + xq - 1) : 0.f;  // left halo (zero pad)
        const float r = (tx < 31) ? __ldg(row + xq + 4) : 0.f;  // right halo (zero pad)

        const float v0 = l,    v1 = cen.x, v2 = cen.y,
                    v3 = cen.z, v4 = cen.w, v5 = r;

        const float w0 = w[dy * 3 + 0];
        const float w1 = w[dy * 3 + 1];
        const float w2 = w[dy * 3 + 2];

        acc0 = fmaf(w0, v0, fmaf(w1, v1, fmaf(w2, v2, acc0)));
        acc1 = fmaf(w0, v1, fmaf(w1, v2, fmaf(w2, v3, acc1)));
        acc2 = fmaf(w0, v2, fmaf(w1, v3, fmaf(w2, v4, acc2)));
        acc3 = fmaf(w0, v3, fmaf(w1, v4, fmaf(w2, v5, acc3)));
    }

    float* orow = out + ((size_t)(b * Cn + c)) * (Hn * Wn) + y * Wn + xq;
    *reinterpret_cast<float4*>(orow) = make_float4(acc0, acc1, acc2, acc3);
}

extern "C" void kernel_launch(void* const* d_in, const int* in_sizes, int n_in,
                              void* d_out, int out_size)
{
    // metadata order: x, wq, wk, wv  (wq/wk are dead — softmax of a scalar is 1)
    const float* x  = (const float*)d_in[0];
    const float* wv = (const float*)d_in[3];
    float* out = (float*)d_out;

    dim3 block(32, ROWS);
    dim3 grid(Hn / ROWS, Cn, Bn);
    dwconv3x3_kernel<<<grid, block>>>(x, wv, out);
}

// round 4
// speedup vs baseline: 1.2806x; 1.2806x over previous
#include <cuda_runtime.h>
#include <cuda_bf16.h>

// out == depthwise 3x3 conv(x, wv, pad=1); attention path is identity
// (softmax over a size-1 axis == 1, so atten@V == V).
//
// One warp = one full 128-wide row (32 lanes x float4); horizontal halos via
// warp shuffle (zero extra loads); register rolling over y so each input row
// is loaded exactly once (18 loads per 16 output rows). Peeled prologue /
// epilogue so the steady-state store is unconditional.
// Targets the R1 L1tex bottleneck (L1=86%, DRAM=44%).

#define Bn 8
#define Cn 256
#define Hn 128
#define Wn 128
#define STRIP 16          // output rows per warp
#define WARPS 8           // warps per block -> one block = one (b,c) image

__device__ __forceinline__ void row_halo(float4 cen, int lane,
                                         float& l, float& r)
{
    l = __shfl_up_sync(0xFFFFFFFFu, cen.w, 1);
    r = __shfl_down_sync(0xFFFFFFFFu, cen.x, 1);
    if (lane == 0)  l = 0.f;   // left border zero pad
    if (lane == 31) r = 0.f;   // right border zero pad
}

__device__ __forceinline__ float4 fma_row(float4 acc, float wa, float wb, float wc,
                                          float v0, float v1, float v2,
                                          float v3, float v4, float v5)
{
    acc.x = fmaf(wa, v0, fmaf(wb, v1, fmaf(wc, v2, acc.x)));
    acc.y = fmaf(wa, v1, fmaf(wb, v2, fmaf(wc, v3, acc.y)));
    acc.z = fmaf(wa, v2, fmaf(wb, v3, fmaf(wc, v4, acc.z)));
    acc.w = fmaf(wa, v3, fmaf(wb, v4, fmaf(wc, v5, acc.w)));
    return acc;
}

__global__ __launch_bounds__(WARPS * 32) void dwconv3x3_roll_kernel(
    const float* __restrict__ x,
    const float* __restrict__ wv,
    float* __restrict__ out)
{
    const int lane = threadIdx.x & 31;
    const int warp = threadIdx.x >> 5;           // 0..7 -> strip index
    const int img_id = blockIdx.x;               // 0..2047 = b*Cn + c
    const int c = img_id & (Cn - 1);

    // Per-channel 3x3 weights: wrow0=(w0,w1,w2), wrow1=(w3,w4,w5), wrow2=(w6,w7,w8)
    const float* wp = wv + c * 9;
    const float w0 = __ldg(wp + 0), w1 = __ldg(wp + 1), w2 = __ldg(wp + 2);
    const float w3 = __ldg(wp + 3), w4 = __ldg(wp + 4), w5 = __ldg(wp + 5);
    const float w6 = __ldg(wp + 6), w7 = __ldg(wp + 7), w8 = __ldg(wp + 8);

    const float* img  = x   + (size_t)img_id * (Hn * Wn);
    float*       oimg = out + (size_t)img_id * (Hn * Wn);

    const int y0 = warp * STRIP;
    const int xq = lane * 4;

    float v0, v1, v2, v3, v4, v5, l, r;
    float4 cen;

    float4 accA = make_float4(0.f, 0.f, 0.f, 0.f);
    float4 accB = make_float4(0.f, 0.f, 0.f, 0.f);
    float4 accC = make_float4(0.f, 0.f, 0.f, 0.f);

    // ---- prologue: input row y0-1 contributes wrow0 to out(y0).
    // (Its wrow1/wrow2 targets belong to the previous warp.)
    if (y0 > 0) {
        cen = *reinterpret_cast<const float4*>(img + (y0 - 1) * Wn + xq);
        row_halo(cen, lane, l, r);
        v0 = l; v1 = cen.x; v2 = cen.y; v3 = cen.z; v4 = cen.w; v5 = r;
        accA = fma_row(accA, w0, w1, w2, v0, v1, v2, v3, v4, v5); // -> out(y0)
    }
    // Invariant entering iter i (yy=y0+i):
    //   accA = out(yy)   partial (wrow0*in(yy-1))
    //   accB = out(yy+1) partial (empty)
    //   accC = out(yy-1) partial (completed this iter by wrow2*in(yy))

    // ---- steady state: input rows y0 .. y0+STRIP-1
#pragma unroll
    for (int i = 0; i < STRIP; ++i) {
        const int yy = y0 + i;
        cen = *reinterpret_cast<const float4*>(img + yy * Wn + xq);
        row_halo(cen, lane, l, r);
        v0 = l; v1 = cen.x; v2 = cen.y; v3 = cen.z; v4 = cen.w; v5 = r;

        accA = fma_row(accA, w3, w4, w5, v0, v1, v2, v3, v4, v5); // center -> out(yy)
        accB = fma_row(accB, w0, w1, w2, v0, v1, v2, v3, v4, v5); // top    -> out(yy+1)
        accC = fma_row(accC, w6, w7, w8, v0, v1, v2, v3, v4, v5); // bottom -> out(yy-1)

        if (i > 0)   // i==0: out(y0-1) is the previous warp's row
            *reinterpret_cast<float4*>(oimg + (yy - 1) * Wn + xq) = accC;

        accC = accA;
        accA = accB;
        accB = make_float4(0.f, 0.f, 0.f, 0.f);
    }

    // ---- epilogue: input row y0+STRIP completes out(y0+STRIP-1)
    {
        const int yy = y0 + STRIP;
        if (yy < Hn) {
            cen = *reinterpret_cast<const float4*>(img + yy * Wn + xq);
            row_halo(cen, lane, l, r);
            v0 = l; v1 = cen.x; v2 = cen.y; v3 = cen.z; v4 = cen.w; v5 = r;
            accC = fma_row(accC, w6, w7, w8, v0, v1, v2, v3, v4, v5);
        }
        *reinterpret_cast<float4*>(oimg + (yy - 1) * Wn + xq) = accC;
    }
}

extern "C" void kernel_launch(void* const* d_in, const int* in_sizes, int n_in,
                              void* d_out, int out_size)
{
    // metadata order: x, wq, wk, wv (wq/wk dead: softmax of a scalar is 1)
    const float* x  = (const float*)d_in[0];
    const float* wv = (const float*)d_in[3];
    float* out = (float*)d_out;

    dwconv3x3_roll_kernel<<<Bn * Cn, WARPS * 32>>>(x, wv, out);
}

// round 5
// speedup vs baseline: 1.2915x; 1.0085x over previous
#include <cuda_runtime.h>
#include <cuda_bf16.h>

// out == depthwise 3x3 conv(x, wv, pad=1); attention path is identity
// (softmax over a size-1 axis == 1, so atten@V == V).
//
// R4: R3 rolling-register kernel + explicit load double-buffering (prefetch
// row yy+1 before computing on row yy) to double per-warp MLP, and streaming
// stores. Targets the R3 latency limit (issue=28%, DRAM=63%).

#define Bn 8
#define Cn 256
#define Hn 128
#define Wn 128
#define STRIP 16          // output rows per warp
#define WARPS 8           // warps per block -> one block = one (b,c) image

__device__ __forceinline__ void row_halo(float4 cen, int lane,
                                         float& l, float& r)
{
    l = __shfl_up_sync(0xFFFFFFFFu, cen.w, 1);
    r = __shfl_down_sync(0xFFFFFFFFu, cen.x, 1);
    if (lane == 0)  l = 0.f;   // left border zero pad
    if (lane == 31) r = 0.f;   // right border zero pad
}

__device__ __forceinline__ float4 fma_row(float4 acc, float wa, float wb, float wc,
                                          float v0, float v1, float v2,
                                          float v3, float v4, float v5)
{
    acc.x = fmaf(wa, v0, fmaf(wb, v1, fmaf(wc, v2, acc.x)));
    acc.y = fmaf(wa, v1, fmaf(wb, v2, fmaf(wc, v3, acc.y)));
    acc.z = fmaf(wa, v2, fmaf(wb, v3, fmaf(wc, v4, acc.z)));
    acc.w = fmaf(wa, v3, fmaf(wb, v4, fmaf(wc, v5, acc.w)));
    return acc;
}

__global__ __launch_bounds__(WARPS * 32) void dwconv3x3_pipe_kernel(
    const float* __restrict__ x,
    const float* __restrict__ wv,
    float* __restrict__ out)
{
    const int lane = threadIdx.x & 31;
    const int warp = threadIdx.x >> 5;           // 0..7 -> strip index
    const int img_id = blockIdx.x;               // 0..2047 = b*Cn + c
    const int c = img_id & (Cn - 1);

    // Per-channel 3x3 weights: wrow0=(w0,w1,w2), wrow1=(w3,w4,w5), wrow2=(w6,w7,w8)
    const float* wp = wv + c * 9;
    const float w0 = __ldg(wp + 0), w1 = __ldg(wp + 1), w2 = __ldg(wp + 2);
    const float w3 = __ldg(wp + 3), w4 = __ldg(wp + 4), w5 = __ldg(wp + 5);
    const float w6 = __ldg(wp + 6), w7 = __ldg(wp + 7), w8 = __ldg(wp + 8);

    const float* img  = x   + (size_t)img_id * (Hn * Wn);
    float*       oimg = out + (size_t)img_id * (Hn * Wn);

    const int y0 = warp * STRIP;
    const int xq = lane * 4;

    float v0, v1, v2, v3, v4, v5, l, r;

    float4 accA = make_float4(0.f, 0.f, 0.f, 0.f);
    float4 accB = make_float4(0.f, 0.f, 0.f, 0.f);
    float4 accC = make_float4(0.f, 0.f, 0.f, 0.f);

    // ---- pipeline prime: cen_cur = row y0-1 (or zero), cen_next = row y0.
    // Both loads are in flight before any FMA executes.
    float4 cen_cur = make_float4(0.f, 0.f, 0.f, 0.f);
    if (y0 > 0)
        cen_cur = *reinterpret_cast<const float4*>(img + (y0 - 1) * Wn + xq);
    float4 cen_next = *reinterpret_cast<const float4*>(img + y0 * Wn + xq);

    // ---- prologue: row y0-1 contributes wrow0 to out(y0).
    if (y0 > 0) {
        row_halo(cen_cur, lane, l, r);
        v0 = l; v1 = cen_cur.x; v2 = cen_cur.y; v3 = cen_cur.z; v4 = cen_cur.w; v5 = r;
        accA = fma_row(accA, w0, w1, w2, v0, v1, v2, v3, v4, v5); // -> out(y0)
    }
    cen_cur = cen_next;

    // Invariant entering iter i (yy=y0+i): cen_cur holds input row yy;
    //   accA = out(yy) partial, accB = out(yy+1) partial, accC = out(yy-1) partial.
#pragma unroll
    for (int i = 0; i < STRIP; ++i) {
        const int yy = y0 + i;

        // Prefetch the next input row (yy+1) before computing on row yy.
        cen_next = make_float4(0.f, 0.f, 0.f, 0.f);
        if (yy + 1 < Hn)    // warp-uniform; false only for last warp's last iter
            cen_next = *reinterpret_cast<const float4*>(img + (yy + 1) * Wn + xq);

        row_halo(cen_cur, lane, l, r);
        v0 = l; v1 = cen_cur.x; v2 = cen_cur.y; v3 = cen_cur.z; v4 = cen_cur.w; v5 = r;

        accA = fma_row(accA, w3, w4, w5, v0, v1, v2, v3, v4, v5); // center -> out(yy)
        accB = fma_row(accB, w0, w1, w2, v0, v1, v2, v3, v4, v5); // top    -> out(yy+1)
        accC = fma_row(accC, w6, w7, w8, v0, v1, v2, v3, v4, v5); // bottom -> out(yy-1)

        if (i > 0)   // i==0: out(y0-1) is the previous warp's row
            __stcs(reinterpret_cast<float4*>(oimg + (yy - 1) * Wn + xq), accC);

        accC = accA;
        accA = accB;
        accB = make_float4(0.f, 0.f, 0.f, 0.f);
        cen_cur = cen_next;
    }

    // ---- epilogue: input row y0+STRIP (zero row if off-image) completes
    // out(y0+STRIP-1). cen_cur already holds it (or zeros).
    {
        row_halo(cen_cur, lane, l, r);
        v0 = l; v1 = cen_cur.x; v2 = cen_cur.y; v3 = cen_cur.z; v4 = cen_cur.w; v5 = r;
        accC = fma_row(accC, w6, w7, w8, v0, v1, v2, v3, v4, v5);
        __stcs(reinterpret_cast<float4*>(oimg + (y0 + STRIP - 1) * Wn + xq), accC);
    }
}

extern "C" void kernel_launch(void* const* d_in, const int* in_sizes, int n_in,
                              void* d_out, int out_size)
{
    // metadata order: x, wq, wk, wv (wq/wk dead: softmax of a scalar is 1)
    const float* x  = (const float*)d_in[0];
    const float* wv = (const float*)d_in[3];
    float* out = (float*)d_out;

    dwconv3x3_pipe_kernel<<<Bn * Cn, WARPS * 32>>>(x, wv, out);
}

// round 6
// speedup vs baseline: 1.3476x; 1.0434x over previous
#include <cuda_runtime.h>
#include <cuda_bf16.h>
#include <cstdint>

// out == depthwise 3x3 conv(x, wv, pad=1); attention path is identity
// (softmax over a size-1 axis == 1, so atten@V == V).
//
// R5: cp.async smem pipeline. One block = one (b,c) image. 5-slot x 16-row
// smem ring (40KB); stage s+3 streams in via cp.async.cg while stage s is
// computed from smem. MLP is now decoupled from registers (R4 was
// latency-bound: DRAM=66%, issue=31%, regs=40). Halos all come from smem,
// so DRAM read traffic is exactly compulsory (each row loaded once).

#define Bn 8
#define Cn 256
#define Hn 128
#define Wn 128
#define STG_ROWS 16
#define NSTAGES  8           // 8 * 16 = 128 rows
#define NSLOTS   5
#define ROWB     (Wn * 4)    // 512 bytes per row

__device__ __forceinline__ void cp16(uint32_t smem_dst, const void* gmem_src) {
    asm volatile("cp.async.cg.shared.global [%0], [%1], 16;\n"
                 :: "r"(smem_dst), "l"(gmem_src));
}
__device__ __forceinline__ void cp_commit() {
    asm volatile("cp.async.commit_group;\n" ::: "memory");
}
template <int N>
__device__ __forceinline__ void cp_wait() {
    asm volatile("cp.async.wait_group %0;\n" :: "n"(N) : "memory");
}

__device__ __forceinline__ void row_halo(float4 cen, int lane, float& l, float& r) {
    l = __shfl_up_sync(0xFFFFFFFFu, cen.w, 1);
    r = __shfl_down_sync(0xFFFFFFFFu, cen.x, 1);
    if (lane == 0)  l = 0.f;
    if (lane == 31) r = 0.f;
}

__device__ __forceinline__ float4 fma_row(float4 acc, float wa, float wb, float wc,
                                          float4 cen, float l, float r) {
    acc.x = fmaf(wa, l,     fmaf(wb, cen.x, fmaf(wc, cen.y, acc.x)));
    acc.y = fmaf(wa, cen.x, fmaf(wb, cen.y, fmaf(wc, cen.z, acc.y)));
    acc.z = fmaf(wa, cen.y, fmaf(wb, cen.z, fmaf(wc, cen.w, acc.z)));
    acc.w = fmaf(wa, cen.z, fmaf(wb, cen.w, fmaf(wc, r,     acc.w)));
    return acc;
}

__global__ __launch_bounds__(256) void dwconv3x3_cpasync_kernel(
    const float* __restrict__ x,
    const float* __restrict__ wv,
    float* __restrict__ out)
{
    __shared__ __align__(16) float ring[NSLOTS * STG_ROWS * Wn];  // 40 KB

    const int tid  = threadIdx.x;
    const int lane = tid & 31;
    const int warp = tid >> 5;                   // 0..7
    const int img_id = blockIdx.x;               // b*Cn + c
    const int c = img_id & (Cn - 1);

    const float* wp = wv + c * 9;
    const float w0 = __ldg(wp + 0), w1 = __ldg(wp + 1), w2 = __ldg(wp + 2);
    const float w3 = __ldg(wp + 3), w4 = __ldg(wp + 4), w5 = __ldg(wp + 5);
    const float w6 = __ldg(wp + 6), w7 = __ldg(wp + 7), w8 = __ldg(wp + 8);

    const float* img  = x   + (size_t)img_id * (Hn * Wn);
    float*       oimg = out + (size_t)img_id * (Hn * Wn);

    const uint32_t ring_u = (uint32_t)__cvta_generic_to_shared(ring);
    const int row_in_stage = tid >> 4;           // 0..15 (16 threads per row)
    const int col_off      = (tid & 15) * 32;    // byte offset within row

    // ---- prologue: issue stages 0,1,2 (slots 0,1,2)
#pragma unroll
    for (int s = 0; s < 3; ++s) {
        const char* g = (const char*)(img + (s * STG_ROWS + row_in_stage) * Wn) + col_off;
        uint32_t d = ring_u + (uint32_t)((s * STG_ROWS + row_in_stage) * ROWB + col_off);
        cp16(d, g);
        cp16(d + 16, g + 16);
        cp_commit();
    }

#pragma unroll
    for (int s = 0; s < NSTAGES; ++s) {
        // Stages <= s+1 must be complete (at most stage s+2 pending).
        if (s < NSTAGES - 2) cp_wait<1>(); else cp_wait<0>();
        __syncthreads();   // make all threads' cp.async data visible block-wide

        // Issue stage s+3 into slot (s+3)%5 (overwrites stage s-2, whose last
        // reader was compute s-1, fenced by the barrier above).
        if (s + 3 < NSTAGES) {
            const int st = s + 3, slot = (s + 3) % NSLOTS;
            const char* g = (const char*)(img + (st * STG_ROWS + row_in_stage) * Wn) + col_off;
            uint32_t d = ring_u + (uint32_t)((slot * STG_ROWS + row_in_stage) * ROWB + col_off);
            cp16(d, g);
            cp16(d + 16, g + 16);
            cp_commit();
        }

        // ---- compute stage s: warp w produces output rows y0, y0+1
        const int y0 = s * STG_ROWS + 2 * warp;

        float4 r0, r1, r2, r3;    // input rows y0-1 .. y0+2
        {
            float4 tmp[4];
#pragma unroll
            for (int k = 0; k < 4; ++k) {
                const int y = y0 - 1 + k;
                if (y >= 0 && y < Hn) {
                    const int slot = (y >> 4) % NSLOTS;   // stage(y) in {s-1,s,s+1}
                    tmp[k] = *reinterpret_cast<const float4*>(
                        ring + (slot * STG_ROWS + (y & 15)) * Wn + lane * 4);
                } else {
                    tmp[k] = make_float4(0.f, 0.f, 0.f, 0.f);
                }
            }
            r0 = tmp[0]; r1 = tmp[1]; r2 = tmp[2]; r3 = tmp[3];
        }

        float l0, h0, l1, h1, l2, h2, l3, h3;
        row_halo(r0, lane, l0, h0);
        row_halo(r1, lane, l1, h1);
        row_halo(r2, lane, l2, h2);
        row_halo(r3, lane, l3, h3);

        float4 acc0 = make_float4(0.f, 0.f, 0.f, 0.f);
        float4 acc1 = make_float4(0.f, 0.f, 0.f, 0.f);
        acc0 = fma_row(acc0, w0, w1, w2, r0, l0, h0);
        acc0 = fma_row(acc0, w3, w4, w5, r1, l1, h1);
        acc0 = fma_row(acc0, w6, w7, w8, r2, l2, h2);
        acc1 = fma_row(acc1, w0, w1, w2, r1, l1, h1);
        acc1 = fma_row(acc1, w3, w4, w5, r2, l2, h2);
        acc1 = fma_row(acc1, w6, w7, w8, r3, l3, h3);

        __stcs(reinterpret_cast<float4*>(oimg + (y0 + 0) * Wn + lane * 4), acc0);
        __stcs(reinterpret_cast<float4*>(oimg + (y0 + 1) * Wn + lane * 4), acc1);
        // No trailing barrier: next iteration's wait+sync fences before the
        // next issue can overwrite any slot still being read.
    }
}

extern "C" void kernel_launch(void* const* d_in, const int* in_sizes, int n_in,
                              void* d_out, int out_size)
{
    // metadata order: x, wq, wk, wv (wq/wk dead: softmax of a scalar is 1)
    const float* x  = (const float*)d_in[0];
    const float* wv = (const float*)d_in[3];
    float* out = (float*)d_out;

    dwconv3x3_cpasync_kernel<<<Bn * Cn, 256>>>(x, wv, out);
}